// round 10
// baseline (speedup 1.0000x reference)
#include <cuda_runtime.h>
#include <cuda_fp16.h>
#include <cstdint>

#define C_CAPS 64
#define S_DIM 2048
#define H_DIM 512
#define M_ROWS (C_CAPS * S_DIM)   // 131072
#define NCHUNK 16
#define CHUNK_S (S_DIM / NCHUNK)  // 128
#define RSTG 16
#define NSTG (CHUNK_S / RSTG)     // 8
#define SLOTS 3

// ---------------- device scratch ----------------
__device__ __align__(128) __half g_whf[(size_t)H_DIM * H_DIM];  // pre-swizzled fp16 W
__device__ float g_norms[4 * M_ROWS];
__device__ float g_b[M_ROWS];
__device__ float g_u[C_CAPS * H_DIM];
__device__ float g_bc[C_CAPS];
__device__ float g_Mp[C_CAPS * NCHUNK];
__device__ float g_Zp[C_CAPS * NCHUNK];
__device__ float g_Wp[C_CAPS * NCHUNK];
__device__ float g_Vp[(size_t)C_CAPS * NCHUNK * H_DIM];
__device__ float g_craw[C_CAPS * H_DIM];
__device__ float g_sqp[C_CAPS * 8];

// ---------------- helpers ----------------
__device__ __forceinline__ uint32_t smem_u32(const void* p) {
    uint32_t a;
    asm("{ .reg .u64 t; cvta.to.shared.u64 t, %1; cvt.u32.u64 %0, t; }" : "=r"(a) : "l"(p));
    return a;
}
__device__ __forceinline__ void ldsm4(uint32_t* r, uint32_t addr) {
    asm volatile("ldmatrix.sync.aligned.m8n8.x4.shared.b16 {%0,%1,%2,%3}, [%4];"
        : "=r"(r[0]), "=r"(r[1]), "=r"(r[2]), "=r"(r[3]) : "r"(addr));
}
// f16-accumulator HMMA
__device__ __forceinline__ void mma16816h(uint32_t* d, const uint32_t* a, const uint32_t* b) {
    asm volatile("mma.sync.aligned.m16n8k16.row.col.f16.f16.f16.f16 "
        "{%0,%1}, {%2,%3,%4,%5}, {%6,%7}, {%0,%1};"
        : "+r"(d[0]), "+r"(d[1])
        : "r"(a[0]), "r"(a[1]), "r"(a[2]), "r"(a[3]), "r"(b[0]), "r"(b[1]));
}
__device__ __forceinline__ void sts128(uint32_t addr, uint4 v) {
    asm volatile("st.shared.v4.b32 [%0], {%1,%2,%3,%4};"
        :: "r"(addr), "r"(v.x), "r"(v.y), "r"(v.z), "r"(v.w) : "memory");
}
#define CP_ASYNC16(dst, src) \
    asm volatile("cp.async.cg.shared.global [%0], [%1], 16;" :: "r"(dst), "l"(src) : "memory")
#define CP_COMMIT() asm volatile("cp.async.commit_group;" ::: "memory")
#define CP_WAIT(n)  asm volatile("cp.async.wait_group %0;" :: "n"(n) : "memory")

__device__ __forceinline__ uint32_t packh2(float x, float y) {
    __half2 h = __floats2half2_rn(x, y);
    return *(uint32_t*)&h;
}
__device__ __forceinline__ uint32_t tswz(uint32_t row, uint32_t kc) {
    return row * 64u + ((kc ^ ((row >> 1) & 3u)) << 4);
}

// ============================================================================
// convw: W fp32 -> pre-swizzled fp16 tiles (8KB blocks [128 rows x 32 k]).
// ============================================================================
__global__ void convw_kernel(const float* __restrict__ W) {
    int g = blockIdx.x * 256 + threadIdx.x;
    int n = g >> 7, ch = g & 127;
    int kt = ch >> 3, kc = (ch >> 1) & 3, half = ch & 1;
    int bn = n >> 7, nrow = n & 127;
    float4 v = *(const float4*)&W[(size_t)n * 512 + ch * 4];
    uint2 hi;
    hi.x = packh2(v.x, v.y);
    hi.y = packh2(v.z, v.w);
    size_t dst = ((size_t)(bn * 16 + kt) << 13) + tswz(nrow, kc) + half * 8;
    *(uint2*)((char*)g_whf + dst) = hi;
}

// ============================================================================
// GEMM (norms only): fp16 x * fp16 W, f16 accumulate. Tile 128x128, BK=32,
// 8 warps, double-buffered. B via cp.async from pre-swizzled W.
// ============================================================================
#define GSM_STAGE 16384
#define GSM_TOTAL (2 * GSM_STAGE + 512)

__device__ __forceinline__ void issueB(uint32_t stg, int bn, int kt, int t) {
    size_t tile = (size_t)(bn * 16 + kt) << 13;
    const char* sh = (const char*)g_whf + tile + t * 32;
    CP_ASYNC16(stg + 8192 + t * 32, sh);
    CP_ASYNC16(stg + 8192 + t * 32 + 16, sh + 16);
}

__global__ void __launch_bounds__(256, 2) gemm_norms(
    const float* __restrict__ x, const float* __restrict__ bias)
{
    extern __shared__ __align__(1024) char smem[];
    const uint32_t sb = smem_u32(smem);

    const int t = threadIdx.x, l = t & 31, wid = t >> 5;
    const int wm = wid & 3, wn = wid >> 2;
    const int bn = blockIdx.x, mtile = blockIdx.y;

    const int c0row = t >> 2, ckc = t & 3;
    const float* ag0 = x + ((size_t)mtile * 128 + c0row) * 512 + ckc * 8;
    const float* ag1 = x + ((size_t)mtile * 128 + c0row + 64) * 512 + ckc * 8;
    const uint32_t so0 = tswz(c0row, ckc);
    const uint32_t so1 = tswz(c0row + 64, ckc);

    uint32_t aoffA[2][2], aoffB[4][2];
#pragma unroll
    for (int mt = 0; mt < 2; mt++)
#pragma unroll
        for (int ks = 0; ks < 2; ks++) {
            uint32_t m = wm * 32 + mt * 16 + ((l >> 3) & 1) * 8 + (l & 7);
            aoffA[mt][ks] = tswz(m, ks * 2 + (l >> 4));
        }
#pragma unroll
    for (int nt2 = 0; nt2 < 4; nt2++)
#pragma unroll
        for (int ks = 0; ks < 2; ks++) {
            uint32_t n = wn * 64 + nt2 * 16 + ((l >> 4) & 1) * 8 + (l & 7);
            aoffB[nt2][ks] = tswz(n, ks * 2 + ((l >> 3) & 1));
        }

    uint32_t acc[2][8][2];
#pragma unroll
    for (int mt = 0; mt < 2; mt++)
#pragma unroll
        for (int nt = 0; nt < 8; nt++) { acc[mt][nt][0] = 0u; acc[mt][nt][1] = 0u; }

    issueB(sb, bn, 0, t);
    CP_COMMIT();
    float4 pa[2][2];
    pa[0][0] = *(const float4*)(ag0); pa[0][1] = *(const float4*)(ag0 + 4);
    pa[1][0] = *(const float4*)(ag1); pa[1][1] = *(const float4*)(ag1 + 4);

    for (int kt = 0; kt < 16; kt++) {
        const uint32_t stg = sb + (kt & 1) * GSM_STAGE;
        {
            uint4 h0, h1;
            h0.x = packh2(pa[0][0].x, pa[0][0].y); h0.y = packh2(pa[0][0].z, pa[0][0].w);
            h0.z = packh2(pa[0][1].x, pa[0][1].y); h0.w = packh2(pa[0][1].z, pa[0][1].w);
            h1.x = packh2(pa[1][0].x, pa[1][0].y); h1.y = packh2(pa[1][0].z, pa[1][0].w);
            h1.z = packh2(pa[1][1].x, pa[1][1].y); h1.w = packh2(pa[1][1].z, pa[1][1].w);
            sts128(stg + so0, h0);
            sts128(stg + so1, h1);
        }
        if (kt < 15) {
            issueB(sb + ((kt + 1) & 1) * GSM_STAGE, bn, kt + 1, t);
            CP_COMMIT();
            CP_WAIT(1);
        } else {
            CP_WAIT(0);
        }
        __syncthreads();

        if (kt < 15) {
            int ko = (kt + 1) * 32;
            pa[0][0] = *(const float4*)(ag0 + ko); pa[0][1] = *(const float4*)(ag0 + ko + 4);
            pa[1][0] = *(const float4*)(ag1 + ko); pa[1][1] = *(const float4*)(ag1 + ko + 4);
        }

#pragma unroll
        for (int ks = 0; ks < 2; ks++) {
            uint32_t ah[2][4], bh[4][4];
#pragma unroll
            for (int mt = 0; mt < 2; mt++) ldsm4(ah[mt], stg + aoffA[mt][ks]);
#pragma unroll
            for (int nt2 = 0; nt2 < 4; nt2++) ldsm4(bh[nt2], stg + 8192 + aoffB[nt2][ks]);
#pragma unroll
            for (int mt = 0; mt < 2; mt++)
#pragma unroll
                for (int nt = 0; nt < 8; nt++)
                    mma16816h(acc[mt][nt], ah[mt], &bh[nt >> 1][(nt & 1) * 2]);
        }
        __syncthreads();
    }

    float* norm_sm = (float*)(smem + 2 * GSM_STAGE);
    if (t < 128) norm_sm[t] = 0.f;
    __syncthreads();

    float2 bias2[8];
#pragma unroll
    for (int nt = 0; nt < 8; nt++)
        bias2[nt] = *(const float2*)&bias[bn * 128 + wn * 64 + nt * 8 + (l & 3) * 2];

#pragma unroll
    for (int mt = 0; mt < 2; mt++)
#pragma unroll
        for (int half = 0; half < 2; half++) {
            int r = wm * 32 + mt * 16 + (l >> 2) + half * 8;
            float ss = 0.f;
#pragma unroll
            for (int nt = 0; nt < 8; nt++) {
                float2 v = __half22float2(*(__half2*)&acc[mt][nt][half]);
                float vx = v.x + bias2[nt].x;
                float vy = v.y + bias2[nt].y;
                ss += vx * vx + vy * vy;
            }
            ss += __shfl_xor_sync(0xffffffffu, ss, 1);
            ss += __shfl_xor_sync(0xffffffffu, ss, 2);
            if ((l & 3) == 0) atomicAdd(&norm_sm[r], ss);
        }
    __syncthreads();
    if (t < 128)
        g_norms[(size_t)bn * M_ROWS + (size_t)mtile * 128 + t] = norm_sm[t];
}

// ============================================================================
// Sweep: 3-slot cp.async ring, 16-row stages (96KB dynamic smem, 2 CTAs/SM).
// ============================================================================
#define SWEEP_SMEM (SLOTS * RSTG * 512 * 4)

__device__ __forceinline__ void sweep_issue(const float* src, float* slot, int t) {
    uint32_t dst = smem_u32(slot);
#pragma unroll
    for (int i = 0; i < 8; i++) {
        int idx = t + 256 * i;
        CP_ASYNC16(dst + idx * 16, src + idx * 4);
    }
    CP_COMMIT();
}

__global__ void __launch_bounds__(256, 2) sweep_pass(const float* __restrict__ x, int do_dot) {
    extern __shared__ __align__(16) float tiles[];
    __shared__ float usm[512];
    __shared__ float bst[RSTG], sst[RSTG], wst[RSTG];
    __shared__ float runMs, Zsh, Wsh, fsh, bcs;

    const int c = blockIdx.y, chunk = blockIdx.x;
    const int t = threadIdx.x, wid = t >> 5, lane = t & 31;

    usm[t]       = do_dot ? g_u[c * 512 + t] : 0.f;
    usm[t + 256] = do_dot ? g_u[c * 512 + t + 256] : 0.f;
    if (t == 0) { runMs = -1e30f; Zsh = 0.f; Wsh = 0.f; bcs = do_dot ? g_bc[c] : 0.f; }

    const size_t rowbase = (size_t)c * S_DIM + (size_t)chunk * CHUNK_S;
    float ax = 0.f, ay = 0.f;

    sweep_issue(x + rowbase * 512, tiles, t);
    sweep_issue(x + (rowbase + RSTG) * 512, tiles + RSTG * 512, t);

    for (int st = 0; st < NSTG; st++) {
        if (st < NSTG - 1) { CP_WAIT(1); } else { CP_WAIT(0); }
        __syncthreads();
        float* tile = tiles + (st % SLOTS) * (RSTG * 512);

        if (st + 2 < NSTG)
            sweep_issue(x + (rowbase + (size_t)(st + 2) * RSTG) * 512,
                        tiles + ((st + 2) % SLOTS) * (RSTG * 512), t);

#pragma unroll
        for (int rr = 0; rr < 2; rr++) {
            int rl = wid * 2 + rr;
            float dot = 0.f;
            if (do_dot) {
                const float4* tr = (const float4*)(tile + rl * 512);
#pragma unroll
                for (int j = 0; j < 4; j++) {
                    float4 v = tr[lane + 32 * j];
                    float4 cv = *(const float4*)&usm[(lane + 32 * j) * 4];
                    dot += v.x * cv.x + v.y * cv.y + v.z * cv.z + v.w * cv.w;
                }
#pragma unroll
                for (int off = 16; off > 0; off >>= 1)
                    dot += __shfl_xor_sync(0xffffffffu, dot, off);
            }
            if (lane == 0) {
                size_t row = rowbase + st * RSTG + rl;
                float sq = g_norms[row] + g_norms[M_ROWS + row]
                         + g_norms[2 * M_ROWS + row] + g_norms[3 * M_ROWS + row];
                float scale = (sq / (1.f + sq)) * rsqrtf(sq + 1e-7f);
                float bv;
                if (do_dot) {
                    bv = g_b[row] + scale * (dot + bcs);
                    g_b[row] = bv;
                } else {
                    bv = 0.f;
                }
                bst[rl] = bv;
                sst[rl] = scale;
            }
        }
        __syncthreads();

        if (t < 32) {
            float v = (lane < RSTG) ? bst[lane] : -1e30f;
            float m = v;
#pragma unroll
            for (int off = 16; off > 0; off >>= 1)
                m = fmaxf(m, __shfl_xor_sync(0xffffffffu, m, off));
            float rm = runMs;
            float nm = fmaxf(rm, m);
            float w = __expf(v - nm);
            float zst = w;
#pragma unroll
            for (int off = 16; off > 0; off >>= 1)
                zst += __shfl_xor_sync(0xffffffffu, zst, off);
            float wsv = (lane < RSTG) ? w * sst[lane] : 0.f;
            float wss = wsv;
#pragma unroll
            for (int off = 16; off > 0; off >>= 1)
                wss += __shfl_xor_sync(0xffffffffu, wss, off);
            if (lane < RSTG) wst[lane] = wsv;
            if (lane == 0) {
                float f = __expf(rm - nm);
                fsh = f;
                Zsh = Zsh * f + zst;
                Wsh = Wsh * f + wss;
                runMs = nm;
            }
        }
        __syncthreads();

        float f = fsh;
        ax *= f; ay *= f;
#pragma unroll
        for (int r = 0; r < RSTG; r++) {
            float w = wst[r];
            float2 v = *(const float2*)(tile + r * 512 + 2 * t);
            ax += w * v.x;
            ay += w * v.y;
        }
    }

    int pc = c * NCHUNK + chunk;
    *(float2*)&g_Vp[(size_t)pc * 512 + 2 * t] = make_float2(ax, ay);
    if (t == 0) { g_Mp[pc] = runMs; g_Zp[pc] = Zsh; g_Wp[pc] = Wsh; }
}

// ============================================================================
// cmat (fused reduce): y from chunk partials; craw = y.W_o + bias_o*wts;
// partial sumsq per (c, ob). grid (8, 64): 64 outputs per block, warp per 8.
// ============================================================================
__global__ void __launch_bounds__(256) cmat_kernel(
    const float* __restrict__ W, const float* __restrict__ bias)
{
    const int ob = blockIdx.x, c = blockIdx.y;
    const int t = threadIdx.x, wid = t >> 5, lane = t & 31;
    __shared__ float ysm[512];
    __shared__ float sk[NCHUNK];
    __shared__ float ssp[8];
    __shared__ float Zs, Wts;

    if (t == 0) {
        float M = g_Mp[c * NCHUNK];
#pragma unroll
        for (int k = 1; k < NCHUNK; k++) M = fmaxf(M, g_Mp[c * NCHUNK + k]);
        float Z = 0.f, Wt = 0.f;
#pragma unroll
        for (int k = 0; k < NCHUNK; k++) {
            float e = __expf(g_Mp[c * NCHUNK + k] - M);
            sk[k] = e;
            Z  += g_Zp[c * NCHUNK + k] * e;
            Wt += g_Wp[c * NCHUNK + k] * e;
        }
        Zs = Z;
        Wts = Wt / Z;
    }
    __syncthreads();

    {
        float w0 = 0.f, w1 = 0.f;
#pragma unroll
        for (int k = 0; k < NCHUNK; k++) {
            float e = sk[k];
            float2 v = *(const float2*)&g_Vp[((size_t)(c * NCHUNK + k)) * 512 + 2 * t];
            w0 += e * v.x;
            w1 += e * v.y;
        }
        float invZ = 1.f / Zs;
        ysm[2 * t] = w0 * invZ;
        ysm[2 * t + 1] = w1 * invZ;
    }
    __syncthreads();

    const float Wts_l = Wts;
    float ss = 0.f;
#pragma unroll
    for (int i = 0; i < 8; i++) {
        int o = ob * 64 + wid * 8 + i;
        const float4* wr = (const float4*)(W + (size_t)o * 512);
        float d = 0.f;
#pragma unroll
        for (int g = 0; g < 4; g++) {
            float4 a = wr[lane + 32 * g];
            float4 b = *(const float4*)&ysm[(lane + 32 * g) * 4];
            d += a.x * b.x + a.y * b.y + a.z * b.z + a.w * b.w;
        }
#pragma unroll
        for (int off = 16; off > 0; off >>= 1)
            d += __shfl_xor_sync(0xffffffffu, d, off);
        if (lane == 0) {
            float cr = d + bias[o] * Wts_l;
            g_craw[c * 512 + o] = cr;
            ss += cr * cr;
        }
    }
    if (lane == 0) ssp[wid] = ss;
    __syncthreads();
    if (t == 0) {
        float s = 0.f;
#pragma unroll
        for (int k = 0; k < 8; k++) s += ssp[k];
        g_sqp[c * 8 + ob] = s;
    }
}

// ============================================================================
// ustep: scale; u = scale * W^T craw ; bc = scale*(bias.craw).
// grid (8, 64): 64 h-columns per block; o-loop split 8 ways (64 each).
// ============================================================================
__global__ void __launch_bounds__(256) ustep_kernel(
    const float* __restrict__ W, const float* __restrict__ bias)
{
    const int ob = blockIdx.x, c = blockIdx.y;
    const int t = threadIdx.x;
    const int og = t >> 5, cp = t & 31;

    __shared__ float csm[512];
    __shared__ float2 up[8][32];
    __shared__ float scsh;
    __shared__ float red2[8];

    csm[t]       = g_craw[c * 512 + t];
    csm[t + 256] = g_craw[c * 512 + t + 256];
    if (t == 0) {
        float sq = 0.f;
#pragma unroll
        for (int k = 0; k < 8; k++) sq += g_sqp[c * 8 + k];
        scsh = (sq / (1.f + sq)) * rsqrtf(sq + 1e-7f);
    }
    __syncthreads();
    const float scale = scsh;

    float u0 = 0.f, u1 = 0.f;
    const float* wp = W + (size_t)(og * 64) * 512 + ob * 64 + cp * 2;
#pragma unroll 8
    for (int o = 0; o < 64; o++) {
        float co = csm[og * 64 + o];
        float2 wv = *(const float2*)(wp + (size_t)o * 512);
        u0 += co * wv.x;
        u1 += co * wv.y;
    }
    up[og][cp] = make_float2(u0, u1);
    __syncthreads();

    if (t < 32) {
        float sx = 0.f, sy = 0.f;
#pragma unroll
        for (int k = 0; k < 8; k++) { sx += up[k][t].x; sy += up[k][t].y; }
        *(float2*)&g_u[c * 512 + ob * 64 + t * 2] =
            make_float2(scale * sx, scale * sy);
    }

    if (ob == 0) {
        float p = bias[t] * csm[t] + bias[t + 256] * csm[t + 256];
#pragma unroll
        for (int off = 16; off > 0; off >>= 1)
            p += __shfl_xor_sync(0xffffffffu, p, off);
        if ((t & 31) == 0) red2[t >> 5] = p;
        __syncthreads();
        if (t == 0) {
            float pp = 0.f;
#pragma unroll
            for (int k = 0; k < 8; k++) pp += red2[k];
            g_bc[c] = scale * pp;
        }
    }
}

// ============================================================================
__global__ void __launch_bounds__(256) out_kernel(float* __restrict__ out) {
    const int c = blockIdx.x, t = threadIdx.x;
    __shared__ float scsh;
    if (t == 0) {
        float sq = 0.f;
#pragma unroll
        for (int k = 0; k < 8; k++) sq += g_sqp[c * 8 + k];
        scsh = (sq / (1.f + sq)) * rsqrtf(sq + 1e-7f);
    }
    __syncthreads();
    out[c * 512 + t]       = scsh * g_craw[c * 512 + t];
    out[c * 512 + t + 256] = scsh * g_craw[c * 512 + t + 256];
}

// ============================================================================
extern "C" void kernel_launch(void* const* d_in, const int* in_sizes, int n_in,
                              void* d_out, int out_size) {
    const float* x    = (const float*)d_in[0];
    const float* W    = (const float*)d_in[1];
    const float* bias = (const float*)d_in[2];
    float* out = (float*)d_out;

    void* pb = nullptr; cudaGetSymbolAddress(&pb, g_b);
    cudaMemsetAsync(pb, 0, (size_t)M_ROWS * sizeof(float));

    convw_kernel<<<256, 256>>>(W);

    static bool attr_done = false;
    if (!attr_done) {
        cudaFuncSetAttribute(gemm_norms, cudaFuncAttributeMaxDynamicSharedMemorySize, GSM_TOTAL);
        cudaFuncSetAttribute(sweep_pass, cudaFuncAttributeMaxDynamicSharedMemorySize, SWEEP_SMEM);
        attr_done = true;
    }
    gemm_norms<<<dim3(4, 1024), 256, GSM_TOTAL>>>(x, bias);

    for (int it = 0; it < 3; ++it) {
        sweep_pass<<<dim3(NCHUNK, C_CAPS), 256, SWEEP_SMEM>>>(x, it > 0 ? 1 : 0);
        cmat_kernel<<<dim3(8, C_CAPS), 256>>>(W, bias);
        if (it < 2) ustep_kernel<<<dim3(8, C_CAPS), 256>>>(W, bias);
        else        out_kernel<<<C_CAPS, 256>>>(out);
    }
}

// round 11
// speedup vs baseline: 1.0006x; 1.0006x over previous
#include <cuda_runtime.h>
#include <cuda_fp16.h>
#include <cstdint>

#define C_CAPS 64
#define S_DIM 2048
#define H_DIM 512
#define M_ROWS (C_CAPS * S_DIM)   // 131072
#define NCHUNK 16
#define CHUNK_S (S_DIM / NCHUNK)  // 128
#define RSTG 16
#define NSTG (CHUNK_S / RSTG)     // 8
#define SLOTS 3

// ---------------- device scratch ----------------
__device__ __align__(128) __half g_whf[(size_t)H_DIM * H_DIM];  // pre-swizzled fp16 W
__device__ float g_norms[4 * M_ROWS];
__device__ float g_b[M_ROWS];
__device__ float g_u[C_CAPS * H_DIM];
__device__ float g_bc[C_CAPS];
__device__ float g_Mp[C_CAPS * NCHUNK];
__device__ float g_Zp[C_CAPS * NCHUNK];
__device__ float g_Wp[C_CAPS * NCHUNK];
__device__ float g_Vp[(size_t)C_CAPS * NCHUNK * H_DIM];
__device__ float g_craw[C_CAPS * H_DIM];
__device__ float g_sqp[C_CAPS * 8];

// ---------------- helpers ----------------
__device__ __forceinline__ uint32_t smem_u32(const void* p) {
    uint32_t a;
    asm("{ .reg .u64 t; cvta.to.shared.u64 t, %1; cvt.u32.u64 %0, t; }" : "=r"(a) : "l"(p));
    return a;
}
__device__ __forceinline__ void ldsm4(uint32_t* r, uint32_t addr) {
    asm volatile("ldmatrix.sync.aligned.m8n8.x4.shared.b16 {%0,%1,%2,%3}, [%4];"
        : "=r"(r[0]), "=r"(r[1]), "=r"(r[2]), "=r"(r[3]) : "r"(addr));
}
// f16-accumulator HMMA
__device__ __forceinline__ void mma16816h(uint32_t* d, const uint32_t* a, const uint32_t* b) {
    asm volatile("mma.sync.aligned.m16n8k16.row.col.f16.f16.f16.f16 "
        "{%0,%1}, {%2,%3,%4,%5}, {%6,%7}, {%0,%1};"
        : "+r"(d[0]), "+r"(d[1])
        : "r"(a[0]), "r"(a[1]), "r"(a[2]), "r"(a[3]), "r"(b[0]), "r"(b[1]));
}
__device__ __forceinline__ void sts128(uint32_t addr, uint4 v) {
    asm volatile("st.shared.v4.b32 [%0], {%1,%2,%3,%4};"
        :: "r"(addr), "r"(v.x), "r"(v.y), "r"(v.z), "r"(v.w) : "memory");
}
#define CP_ASYNC16(dst, src) \
    asm volatile("cp.async.cg.shared.global [%0], [%1], 16;" :: "r"(dst), "l"(src) : "memory")
#define CP_COMMIT() asm volatile("cp.async.commit_group;" ::: "memory")
#define CP_WAIT(n)  asm volatile("cp.async.wait_group %0;" :: "n"(n) : "memory")

__device__ __forceinline__ uint32_t packh2(float x, float y) {
    __half2 h = __floats2half2_rn(x, y);
    return *(uint32_t*)&h;
}
__device__ __forceinline__ uint32_t tswz(uint32_t row, uint32_t kc) {
    return row * 64u + ((kc ^ ((row >> 1) & 3u)) << 4);
}

// ============================================================================
// convw: W fp32 -> pre-swizzled fp16 tiles (8KB blocks [128 rows x 32 k]).
// ============================================================================
__global__ void convw_kernel(const float* __restrict__ W) {
    int g = blockIdx.x * 256 + threadIdx.x;
    int n = g >> 7, ch = g & 127;
    int kt = ch >> 3, kc = (ch >> 1) & 3, half = ch & 1;
    int bn = n >> 7, nrow = n & 127;
    float4 v = *(const float4*)&W[(size_t)n * 512 + ch * 4];
    uint2 hi;
    hi.x = packh2(v.x, v.y);
    hi.y = packh2(v.z, v.w);
    size_t dst = ((size_t)(bn * 16 + kt) << 13) + tswz(nrow, kc) + half * 8;
    *(uint2*)((char*)g_whf + dst) = hi;
}

// ============================================================================
// GEMM (norms only): fp16 x * fp16 W, f16 accumulate. Tile 128x128, BK=32,
// 8 warps, double-buffered. B via cp.async from pre-swizzled W.
// ============================================================================
#define GSM_STAGE 16384
#define GSM_TOTAL (2 * GSM_STAGE + 512)

__device__ __forceinline__ void issueB(uint32_t stg, int bn, int kt, int t) {
    size_t tile = (size_t)(bn * 16 + kt) << 13;
    const char* sh = (const char*)g_whf + tile + t * 32;
    CP_ASYNC16(stg + 8192 + t * 32, sh);
    CP_ASYNC16(stg + 8192 + t * 32 + 16, sh + 16);
}

__global__ void __launch_bounds__(256, 2) gemm_norms(
    const float* __restrict__ x, const float* __restrict__ bias)
{
    extern __shared__ __align__(1024) char smem[];
    const uint32_t sb = smem_u32(smem);

    const int t = threadIdx.x, l = t & 31, wid = t >> 5;
    const int wm = wid & 3, wn = wid >> 2;
    const int bn = blockIdx.x, mtile = blockIdx.y;

    const int c0row = t >> 2, ckc = t & 3;
    const float* ag0 = x + ((size_t)mtile * 128 + c0row) * 512 + ckc * 8;
    const float* ag1 = x + ((size_t)mtile * 128 + c0row + 64) * 512 + ckc * 8;
    const uint32_t so0 = tswz(c0row, ckc);
    const uint32_t so1 = tswz(c0row + 64, ckc);

    uint32_t aoffA[2][2], aoffB[4][2];
#pragma unroll
    for (int mt = 0; mt < 2; mt++)
#pragma unroll
        for (int ks = 0; ks < 2; ks++) {
            uint32_t m = wm * 32 + mt * 16 + ((l >> 3) & 1) * 8 + (l & 7);
            aoffA[mt][ks] = tswz(m, ks * 2 + (l >> 4));
        }
#pragma unroll
    for (int nt2 = 0; nt2 < 4; nt2++)
#pragma unroll
        for (int ks = 0; ks < 2; ks++) {
            uint32_t n = wn * 64 + nt2 * 16 + ((l >> 4) & 1) * 8 + (l & 7);
            aoffB[nt2][ks] = tswz(n, ks * 2 + ((l >> 3) & 1));
        }

    uint32_t acc[2][8][2];
#pragma unroll
    for (int mt = 0; mt < 2; mt++)
#pragma unroll
        for (int nt = 0; nt < 8; nt++) { acc[mt][nt][0] = 0u; acc[mt][nt][1] = 0u; }

    issueB(sb, bn, 0, t);
    CP_COMMIT();
    float4 pa[2][2];
    pa[0][0] = *(const float4*)(ag0); pa[0][1] = *(const float4*)(ag0 + 4);
    pa[1][0] = *(const float4*)(ag1); pa[1][1] = *(const float4*)(ag1 + 4);

    for (int kt = 0; kt < 16; kt++) {
        const uint32_t stg = sb + (kt & 1) * GSM_STAGE;
        {
            uint4 h0, h1;
            h0.x = packh2(pa[0][0].x, pa[0][0].y); h0.y = packh2(pa[0][0].z, pa[0][0].w);
            h0.z = packh2(pa[0][1].x, pa[0][1].y); h0.w = packh2(pa[0][1].z, pa[0][1].w);
            h1.x = packh2(pa[1][0].x, pa[1][0].y); h1.y = packh2(pa[1][0].z, pa[1][0].w);
            h1.z = packh2(pa[1][1].x, pa[1][1].y); h1.w = packh2(pa[1][1].z, pa[1][1].w);
            sts128(stg + so0, h0);
            sts128(stg + so1, h1);
        }
        if (kt < 15) {
            issueB(sb + ((kt + 1) & 1) * GSM_STAGE, bn, kt + 1, t);
            CP_COMMIT();
            CP_WAIT(1);
        } else {
            CP_WAIT(0);
        }
        __syncthreads();

        if (kt < 15) {
            int ko = (kt + 1) * 32;
            pa[0][0] = *(const float4*)(ag0 + ko); pa[0][1] = *(const float4*)(ag0 + ko + 4);
            pa[1][0] = *(const float4*)(ag1 + ko); pa[1][1] = *(const float4*)(ag1 + ko + 4);
        }

#pragma unroll
        for (int ks = 0; ks < 2; ks++) {
            uint32_t ah[2][4], bh[4][4];
#pragma unroll
            for (int mt = 0; mt < 2; mt++) ldsm4(ah[mt], stg + aoffA[mt][ks]);
#pragma unroll
            for (int nt2 = 0; nt2 < 4; nt2++) ldsm4(bh[nt2], stg + 8192 + aoffB[nt2][ks]);
#pragma unroll
            for (int mt = 0; mt < 2; mt++)
#pragma unroll
                for (int nt = 0; nt < 8; nt++)
                    mma16816h(acc[mt][nt], ah[mt], &bh[nt >> 1][(nt & 1) * 2]);
        }
        __syncthreads();
    }

    float* norm_sm = (float*)(smem + 2 * GSM_STAGE);
    if (t < 128) norm_sm[t] = 0.f;
    __syncthreads();

    float2 bias2[8];
#pragma unroll
    for (int nt = 0; nt < 8; nt++)
        bias2[nt] = *(const float2*)&bias[bn * 128 + wn * 64 + nt * 8 + (l & 3) * 2];

#pragma unroll
    for (int mt = 0; mt < 2; mt++)
#pragma unroll
        for (int half = 0; half < 2; half++) {
            int r = wm * 32 + mt * 16 + (l >> 2) + half * 8;
            float ss = 0.f;
#pragma unroll
            for (int nt = 0; nt < 8; nt++) {
                float2 v = __half22float2(*(__half2*)&acc[mt][nt][half]);
                float vx = v.x + bias2[nt].x;
                float vy = v.y + bias2[nt].y;
                ss += vx * vx + vy * vy;
            }
            ss += __shfl_xor_sync(0xffffffffu, ss, 1);
            ss += __shfl_xor_sync(0xffffffffu, ss, 2);
            if ((l & 3) == 0) atomicAdd(&norm_sm[r], ss);
        }
    __syncthreads();
    if (t < 128)
        g_norms[(size_t)bn * M_ROWS + (size_t)mtile * 128 + t] = norm_sm[t];
}

// ============================================================================
// Sweep: 3-slot cp.async ring, 16-row stages (96KB dynamic smem, 2 CTAs/SM).
// ============================================================================
#define SWEEP_SMEM (SLOTS * RSTG * 512 * 4)

__device__ __forceinline__ void sweep_issue(const float* src, float* slot, int t) {
    uint32_t dst = smem_u32(slot);
#pragma unroll
    for (int i = 0; i < 8; i++) {
        int idx = t + 256 * i;
        CP_ASYNC16(dst + idx * 16, src + idx * 4);
    }
    CP_COMMIT();
}

__global__ void __launch_bounds__(256, 2) sweep_pass(const float* __restrict__ x, int do_dot) {
    extern __shared__ __align__(16) float tiles[];
    __shared__ float usm[512];
    __shared__ float bst[RSTG], sst[RSTG], wst[RSTG];
    __shared__ float runMs, Zsh, Wsh, fsh, bcs;

    const int c = blockIdx.y, chunk = blockIdx.x;
    const int t = threadIdx.x, wid = t >> 5, lane = t & 31;

    usm[t]       = do_dot ? g_u[c * 512 + t] : 0.f;
    usm[t + 256] = do_dot ? g_u[c * 512 + t + 256] : 0.f;
    if (t == 0) { runMs = -1e30f; Zsh = 0.f; Wsh = 0.f; bcs = do_dot ? g_bc[c] : 0.f; }

    const size_t rowbase = (size_t)c * S_DIM + (size_t)chunk * CHUNK_S;
    float ax = 0.f, ay = 0.f;

    sweep_issue(x + rowbase * 512, tiles, t);
    sweep_issue(x + (rowbase + RSTG) * 512, tiles + RSTG * 512, t);

    for (int st = 0; st < NSTG; st++) {
        if (st < NSTG - 1) { CP_WAIT(1); } else { CP_WAIT(0); }
        __syncthreads();
        float* tile = tiles + (st % SLOTS) * (RSTG * 512);

        if (st + 2 < NSTG)
            sweep_issue(x + (rowbase + (size_t)(st + 2) * RSTG) * 512,
                        tiles + ((st + 2) % SLOTS) * (RSTG * 512), t);

#pragma unroll
        for (int rr = 0; rr < 2; rr++) {
            int rl = wid * 2 + rr;
            float dot = 0.f;
            if (do_dot) {
                const float4* tr = (const float4*)(tile + rl * 512);
#pragma unroll
                for (int j = 0; j < 4; j++) {
                    float4 v = tr[lane + 32 * j];
                    float4 cv = *(const float4*)&usm[(lane + 32 * j) * 4];
                    dot += v.x * cv.x + v.y * cv.y + v.z * cv.z + v.w * cv.w;
                }
#pragma unroll
                for (int off = 16; off > 0; off >>= 1)
                    dot += __shfl_xor_sync(0xffffffffu, dot, off);
            }
            if (lane == 0) {
                size_t row = rowbase + st * RSTG + rl;
                float sq = g_norms[row] + g_norms[M_ROWS + row]
                         + g_norms[2 * M_ROWS + row] + g_norms[3 * M_ROWS + row];
                float scale = (sq / (1.f + sq)) * rsqrtf(sq + 1e-7f);
                float bv;
                if (do_dot) {
                    bv = g_b[row] + scale * (dot + bcs);
                    g_b[row] = bv;
                } else {
                    bv = 0.f;
                }
                bst[rl] = bv;
                sst[rl] = scale;
            }
        }
        __syncthreads();

        if (t < 32) {
            float v = (lane < RSTG) ? bst[lane] : -1e30f;
            float m = v;
#pragma unroll
            for (int off = 16; off > 0; off >>= 1)
                m = fmaxf(m, __shfl_xor_sync(0xffffffffu, m, off));
            float rm = runMs;
            float nm = fmaxf(rm, m);
            float w = __expf(v - nm);
            float zst = w;
#pragma unroll
            for (int off = 16; off > 0; off >>= 1)
                zst += __shfl_xor_sync(0xffffffffu, zst, off);
            float wsv = (lane < RSTG) ? w * sst[lane] : 0.f;
            float wss = wsv;
#pragma unroll
            for (int off = 16; off > 0; off >>= 1)
                wss += __shfl_xor_sync(0xffffffffu, wss, off);
            if (lane < RSTG) wst[lane] = wsv;
            if (lane == 0) {
                float f = __expf(rm - nm);
                fsh = f;
                Zsh = Zsh * f + zst;
                Wsh = Wsh * f + wss;
                runMs = nm;
            }
        }
        __syncthreads();

        float f = fsh;
        ax *= f; ay *= f;
#pragma unroll
        for (int r = 0; r < RSTG; r++) {
            float w = wst[r];
            float2 v = *(const float2*)(tile + r * 512 + 2 * t);
            ax += w * v.x;
            ay += w * v.y;
        }
    }

    int pc = c * NCHUNK + chunk;
    *(float2*)&g_Vp[(size_t)pc * 512 + 2 * t] = make_float2(ax, ay);
    if (t == 0) { g_Mp[pc] = runMs; g_Zp[pc] = Zsh; g_Wp[pc] = Wsh; }
}

// ============================================================================
// cmat (fused reduce): y from chunk partials; craw = y.W_o + bias_o*wts;
// partial sumsq per (c, ob). grid (8, 64): 64 outputs per block, warp per 8.
// ============================================================================
__global__ void __launch_bounds__(256) cmat_kernel(
    const float* __restrict__ W, const float* __restrict__ bias)
{
    const int ob = blockIdx.x, c = blockIdx.y;
    const int t = threadIdx.x, wid = t >> 5, lane = t & 31;
    __shared__ float ysm[512];
    __shared__ float sk[NCHUNK];
    __shared__ float ssp[8];
    __shared__ float Zs, Wts;

    if (t == 0) {
        float M = g_Mp[c * NCHUNK];
#pragma unroll
        for (int k = 1; k < NCHUNK; k++) M = fmaxf(M, g_Mp[c * NCHUNK + k]);
        float Z = 0.f, Wt = 0.f;
#pragma unroll
        for (int k = 0; k < NCHUNK; k++) {
            float e = __expf(g_Mp[c * NCHUNK + k] - M);
            sk[k] = e;
            Z  += g_Zp[c * NCHUNK + k] * e;
            Wt += g_Wp[c * NCHUNK + k] * e;
        }
        Zs = Z;
        Wts = Wt / Z;
    }
    __syncthreads();

    {
        float w0 = 0.f, w1 = 0.f;
#pragma unroll
        for (int k = 0; k < NCHUNK; k++) {
            float e = sk[k];
            float2 v = *(const float2*)&g_Vp[((size_t)(c * NCHUNK + k)) * 512 + 2 * t];
            w0 += e * v.x;
            w1 += e * v.y;
        }
        float invZ = 1.f / Zs;
        ysm[2 * t] = w0 * invZ;
        ysm[2 * t + 1] = w1 * invZ;
    }
    __syncthreads();

    const float Wts_l = Wts;
    float ss = 0.f;
#pragma unroll
    for (int i = 0; i < 8; i++) {
        int o = ob * 64 + wid * 8 + i;
        const float4* wr = (const float4*)(W + (size_t)o * 512);
        float d = 0.f;
#pragma unroll
        for (int g = 0; g < 4; g++) {
            float4 a = wr[lane + 32 * g];
            float4 b = *(const float4*)&ysm[(lane + 32 * g) * 4];
            d += a.x * b.x + a.y * b.y + a.z * b.z + a.w * b.w;
        }
#pragma unroll
        for (int off = 16; off > 0; off >>= 1)
            d += __shfl_xor_sync(0xffffffffu, d, off);
        if (lane == 0) {
            float cr = d + bias[o] * Wts_l;
            g_craw[c * 512 + o] = cr;
            ss += cr * cr;
        }
    }
    if (lane == 0) ssp[wid] = ss;
    __syncthreads();
    if (t == 0) {
        float s = 0.f;
#pragma unroll
        for (int k = 0; k < 8; k++) s += ssp[k];
        g_sqp[c * 8 + ob] = s;
    }
}

// ============================================================================
// ustep: scale; u = scale * W^T craw ; bc = scale*(bias.craw).
// grid (8, 64): 64 h-columns per block; o-loop split 8 ways (64 each).
// ============================================================================
__global__ void __launch_bounds__(256) ustep_kernel(
    const float* __restrict__ W, const float* __restrict__ bias)
{
    const int ob = blockIdx.x, c = blockIdx.y;
    const int t = threadIdx.x;
    const int og = t >> 5, cp = t & 31;

    __shared__ float csm[512];
    __shared__ float2 up[8][32];
    __shared__ float scsh;
    __shared__ float red2[8];

    csm[t]       = g_craw[c * 512 + t];
    csm[t + 256] = g_craw[c * 512 + t + 256];
    if (t == 0) {
        float sq = 0.f;
#pragma unroll
        for (int k = 0; k < 8; k++) sq += g_sqp[c * 8 + k];
        scsh = (sq / (1.f + sq)) * rsqrtf(sq + 1e-7f);
    }
    __syncthreads();
    const float scale = scsh;

    float u0 = 0.f, u1 = 0.f;
    const float* wp = W + (size_t)(og * 64) * 512 + ob * 64 + cp * 2;
#pragma unroll 8
    for (int o = 0; o < 64; o++) {
        float co = csm[og * 64 + o];
        float2 wv = *(const float2*)(wp + (size_t)o * 512);
        u0 += co * wv.x;
        u1 += co * wv.y;
    }
    up[og][cp] = make_float2(u0, u1);
    __syncthreads();

    if (t < 32) {
        float sx = 0.f, sy = 0.f;
#pragma unroll
        for (int k = 0; k < 8; k++) { sx += up[k][t].x; sy += up[k][t].y; }
        *(float2*)&g_u[c * 512 + ob * 64 + t * 2] =
            make_float2(scale * sx, scale * sy);
    }

    if (ob == 0) {
        float p = bias[t] * csm[t] + bias[t + 256] * csm[t + 256];
#pragma unroll
        for (int off = 16; off > 0; off >>= 1)
            p += __shfl_xor_sync(0xffffffffu, p, off);
        if ((t & 31) == 0) red2[t >> 5] = p;
        __syncthreads();
        if (t == 0) {
            float pp = 0.f;
#pragma unroll
            for (int k = 0; k < 8; k++) pp += red2[k];
            g_bc[c] = scale * pp;
        }
    }
}

// ============================================================================
__global__ void __launch_bounds__(256) out_kernel(float* __restrict__ out) {
    const int c = blockIdx.x, t = threadIdx.x;
    __shared__ float scsh;
    if (t == 0) {
        float sq = 0.f;
#pragma unroll
        for (int k = 0; k < 8; k++) sq += g_sqp[c * 8 + k];
        scsh = (sq / (1.f + sq)) * rsqrtf(sq + 1e-7f);
    }
    __syncthreads();
    out[c * 512 + t]       = scsh * g_craw[c * 512 + t];
    out[c * 512 + t + 256] = scsh * g_craw[c * 512 + t + 256];
}

// ============================================================================
extern "C" void kernel_launch(void* const* d_in, const int* in_sizes, int n_in,
                              void* d_out, int out_size) {
    const float* x    = (const float*)d_in[0];
    const float* W    = (const float*)d_in[1];
    const float* bias = (const float*)d_in[2];
    float* out = (float*)d_out;

    void* pb = nullptr; cudaGetSymbolAddress(&pb, g_b);
    cudaMemsetAsync(pb, 0, (size_t)M_ROWS * sizeof(float));

    convw_kernel<<<256, 256>>>(W);

    static bool attr_done = false;
    if (!attr_done) {
        cudaFuncSetAttribute(gemm_norms, cudaFuncAttributeMaxDynamicSharedMemorySize, GSM_TOTAL);
        cudaFuncSetAttribute(sweep_pass, cudaFuncAttributeMaxDynamicSharedMemorySize, SWEEP_SMEM);
        attr_done = true;
    }
    gemm_norms<<<dim3(4, 1024), 256, GSM_TOTAL>>>(x, bias);

    for (int it = 0; it < 3; ++it) {
        sweep_pass<<<dim3(NCHUNK, C_CAPS), 256, SWEEP_SMEM>>>(x, it > 0 ? 1 : 0);
        cmat_kernel<<<dim3(8, C_CAPS), 256>>>(W, bias);
        if (it < 2) ustep_kernel<<<dim3(8, C_CAPS), 256>>>(W, bias);
        else        out_kernel<<<C_CAPS, 256>>>(out);
    }
}